// round 3
// baseline (speedup 1.0000x reference)
#include <cuda_runtime.h>

#define NB 256
#define LSEQ 100

// Scratch: [b][mod][proj(Q,K,V)][640][100] fp32
__device__ float g_scr[196608000UL];

struct Params {
    const float* w[24];  // [mod][wq,wk,wv,bq,bk,bv]
};

__device__ __forceinline__ unsigned long long pack2(float x, float y) {
    unsigned long long r;
    asm("mov.b64 %0, {%1, %2};" : "=l"(r) : "f"(x), "f"(y));
    return r;
}
__device__ __forceinline__ void unpack2(unsigned long long v, float& x, float& y) {
    asm("mov.b64 {%0, %1}, %2;" : "=f"(x), "=f"(y) : "l"(v));
}
__device__ __forceinline__ void ffma2(unsigned long long& c, unsigned long long a, unsigned long long b) {
    asm("fma.rn.f32x2 %0, %1, %2, %0;" : "+l"(c) : "l"(a), "l"(b));
}

// ============================================================================
// Pass 1: QKV projections.  Y[640,100] = W[640,Cin] @ X[Cin,100] + bias
// CTA tile: 128(M) x 100(N). 320 threads, thread tile 8x5, f32x2 along M.
// ============================================================================
__global__ __launch_bounds__(320, 2) void qkv_kernel(const float* __restrict__ x, Params p) {
    const int tid = threadIdx.x;
    int bid = blockIdx.x;
    const int mtile = bid % 5; bid /= 5;
    const int proj  = bid % 3; bid /= 3;
    const int mod   = bid & 3;
    const int b     = bid >> 2;

    const int Cin = (mod == 1) ? 1280 : 640;
    const int ch0 = (mod == 0) ? 8 : (mod == 1) ? 2 : (mod == 2) ? 6 : 0;

    const float* __restrict__ W    = p.w[mod * 6 + proj];
    const float* __restrict__ bias = p.w[mod * 6 + 3 + proj];
    const float* __restrict__ X    = x + (size_t)b * 320000 + (size_t)ch0 * 32000;
    const int mbase = mtile * 128;
    float* __restrict__ O = g_scr + ((((size_t)b * 4 + mod) * 3 + proj) * 640 + mbase) * 100;

    __shared__ __align__(16) float As[16][132];   // k-major, padded
    __shared__ __align__(16) float Bs[16][100];

    const int tn = tid % 20, tm = tid / 20;   // tm 0..15
    const int n0 = tn * 5, m0 = tm * 8;

    unsigned long long acc[4][5];
    #pragma unroll
    for (int i = 0; i < 4; i++)
        #pragma unroll
        for (int j = 0; j < 5; j++) acc[i][j] = 0ULL;

    for (int k0 = 0; k0 < Cin; k0 += 16) {
        // A tile: 128 rows x 16 k, transposed into As[k][m]
        for (int idx = tid; idx < 512; idx += 320) {
            int row = idx >> 2, kq = (idx & 3) << 2;
            float4 v = *(const float4*)(W + (size_t)(mbase + row) * Cin + k0 + kq);
            As[kq + 0][row] = v.x; As[kq + 1][row] = v.y;
            As[kq + 2][row] = v.z; As[kq + 3][row] = v.w;
        }
        // B tile: 16 rows x 100
        for (int idx = tid; idx < 400; idx += 320) {
            int row = idx / 25, c4 = (idx % 25) * 4;
            *(float4*)&Bs[row][c4] = *(const float4*)(X + (size_t)(k0 + row) * 100 + c4);
        }
        __syncthreads();
        #pragma unroll
        for (int kk = 0; kk < 16; kk++) {
            float4 a0 = *(const float4*)&As[kk][m0];
            float4 a1 = *(const float4*)&As[kk][m0 + 4];
            unsigned long long ap0 = pack2(a0.x, a0.y), ap1 = pack2(a0.z, a0.w);
            unsigned long long ap2 = pack2(a1.x, a1.y), ap3 = pack2(a1.z, a1.w);
            #pragma unroll
            for (int j = 0; j < 5; j++) {
                float bv = Bs[kk][n0 + j];
                unsigned long long bb = pack2(bv, bv);
                ffma2(acc[0][j], ap0, bb);
                ffma2(acc[1][j], ap1, bb);
                ffma2(acc[2][j], ap2, bb);
                ffma2(acc[3][j], ap3, bb);
            }
        }
        __syncthreads();
    }

    #pragma unroll
    for (int i = 0; i < 4; i++) {
        int r = m0 + 2 * i;
        float b0 = bias[mbase + r], b1 = bias[mbase + r + 1];
        #pragma unroll
        for (int j = 0; j < 5; j++) {
            float lo, hi;
            unpack2(acc[i][j], lo, hi);
            O[(size_t)r * 100 + n0 + j]       = lo + b0;
            O[(size_t)(r + 1) * 100 + n0 + j] = hi + b1;
        }
    }
}

// ============================================================================
// Pass 2: attention.  One CTA per (b, mod, L-half).  256 threads.
// ============================================================================
__global__ __launch_bounds__(256) void attn_kernel(float* __restrict__ out) {
    const int tid = threadIdx.x;
    int bid = blockIdx.x;
    const int half = bid & 1;
    const int bm   = bid >> 1;
    const int mod  = bm & 3;
    const int b    = bm >> 2;

    const float* __restrict__ Q = g_scr + (size_t)bm * 3 * 64000;
    const float* __restrict__ K = Q + 64000;
    const float* __restrict__ V = Q + 128000;
    float* __restrict__ O = out + ((size_t)mod * NB + b) * 64000;

    __shared__ __align__(16) float Ss[50][101];   // 20200 B
    __shared__ __align__(16) float u[4864];       // Qc[32][52] | Kc[32][100]  (aliased by Vc[40][101])

    // ---- Phase A: S = Q^T K over k-chunks of 32 ----
    const bool act = tid < 250;
    const int lg = tid % 25, mg = tid / 25;   // mg 0..10 (10 inactive)
    const int l0 = lg * 2, m0 = mg * 10;
    const int colQ = half * 50;

    unsigned long long sacc[10];
    #pragma unroll
    for (int j = 0; j < 10; j++) sacc[j] = 0ULL;

    for (int c0 = 0; c0 < 640; c0 += 32) {
        for (int idx = tid; idx < 800; idx += 256) {       // Qc: 32 x 50 (float2)
            int row = idx / 25, c2 = (idx % 25) * 2;
            *(float2*)&u[row * 52 + c2] = *(const float2*)(Q + (size_t)(c0 + row) * 100 + colQ + c2);
        }
        for (int idx = tid; idx < 800; idx += 256) {       // Kc: 32 x 100 (float4)
            int row = idx / 25, c4 = (idx % 25) * 4;
            *(float4*)&u[1664 + row * 100 + c4] = *(const float4*)(K + (size_t)(c0 + row) * 100 + c4);
        }
        __syncthreads();
        if (act) {
            #pragma unroll
            for (int kk = 0; kk < 32; kk++) {
                float2 q2 = *(const float2*)&u[kk * 52 + l0];
                unsigned long long qp = pack2(q2.x, q2.y);
                #pragma unroll
                for (int j = 0; j < 10; j++) {
                    float kv = u[1664 + kk * 100 + m0 + j];
                    ffma2(sacc[j], qp, pack2(kv, kv));
                }
            }
        }
        __syncthreads();
    }
    if (act) {
        #pragma unroll
        for (int j = 0; j < 10; j++) {
            float lo, hi;
            unpack2(sacc[j], lo, hi);
            Ss[l0][m0 + j]     = lo;
            Ss[l0 + 1][m0 + j] = hi;
        }
    }
    __syncthreads();

    // ---- Phase B: softmax over 100 cols, rows 0..49 ----
    {
        const int warp = tid >> 5, lane = tid & 31;
        for (int r = warp; r < 50; r += 8) {
            float v0 = Ss[r][lane];
            float v1 = Ss[r][lane + 32];
            float v2 = Ss[r][lane + 64];
            float v3 = (lane < 4) ? Ss[r][lane + 96] : -3.4e38f;
            float mx = fmaxf(fmaxf(v0, v1), fmaxf(v2, v3));
            #pragma unroll
            for (int o = 16; o; o >>= 1) mx = fmaxf(mx, __shfl_xor_sync(0xffffffffu, mx, o));
            v0 = __expf(v0 - mx);
            v1 = __expf(v1 - mx);
            v2 = __expf(v2 - mx);
            v3 = (lane < 4) ? __expf(v3 - mx) : 0.0f;
            float s = v0 + v1 + v2 + v3;
            #pragma unroll
            for (int o = 16; o; o >>= 1) s += __shfl_xor_sync(0xffffffffu, s, o);
            float inv = 1.0f / s;
            Ss[r][lane]      = v0 * inv;
            Ss[r][lane + 32] = v1 * inv;
            Ss[r][lane + 64] = v2 * inv;
            if (lane < 4) Ss[r][lane + 96] = v3 * inv;
        }
    }

    // ---- Phase C: O = V @ P^T, V in chunks of 40 rows (reuses u as Vc[40][101]) ----
    const int cg = tid % 10, ig = tid / 10;   // ig 0..25 (25 inactive)
    const bool actC = tid < 250;
    const int cl0 = cg * 4, i0 = ig * 2;

    for (int chunk = 0; chunk < 16; chunk++) {
        __syncthreads();   // previous Vc consumers done (covers softmax too on iter 0)
        for (int idx = tid; idx < 1000; idx += 256) {
            int row = idx / 25, c4 = (idx % 25) * 4;
            float4 v = *(const float4*)(V + (size_t)(chunk * 40 + row) * 100 + c4);
            u[row * 101 + c4 + 0] = v.x;
            u[row * 101 + c4 + 1] = v.y;
            u[row * 101 + c4 + 2] = v.z;
            u[row * 101 + c4 + 3] = v.w;
        }
        __syncthreads();
        if (actC) {
            float acc[4][2] = {};
            #pragma unroll 4
            for (int j = 0; j < 100; j++) {
                float p0 = Ss[i0][j], p1 = Ss[i0 + 1][j];
                #pragma unroll
                for (int uu = 0; uu < 4; uu++) {
                    float vv = u[(cl0 + uu) * 101 + j];
                    acc[uu][0] += vv * p0;
                    acc[uu][1] += vv * p1;
                }
            }
            #pragma unroll
            for (int uu = 0; uu < 4; uu++) {
                int c = chunk * 40 + cl0 + uu;
                O[(size_t)c * 100 + half * 50 + i0]     = acc[uu][0];
                O[(size_t)c * 100 + half * 50 + i0 + 1] = acc[uu][1];
            }
        }
    }
}

extern "C" void kernel_launch(void* const* d_in, const int* in_sizes, int n_in,
                              void* d_out, int out_size) {
    const float* x = (const float*)d_in[0];
    Params p;
    for (int i = 0; i < 24; i++) p.w[i] = (const float*)d_in[1 + i];

    qkv_kernel<<<15360, 320>>>(x, p);
    attn_kernel<<<2048, 256>>>((float*)d_out);
}

// round 5
// speedup vs baseline: 2.1281x; 2.1281x over previous
#include <cuda_runtime.h>
#include <cuda_bf16.h>
#include <cstdint>

#define NB 256

// Scratch: [b][mod][proj(Q,K,V)][640][100] fp32
__device__ float g_scr[196608000UL];
__device__ __nv_bfloat16 g_w_hi[6144000];
__device__ __nv_bfloat16 g_w_lo[6144000];
__device__ __nv_bfloat16 g_xt_hi[81920000UL];   // [b][l=100][c=3200]
__device__ __nv_bfloat16 g_xt_lo[81920000UL];

struct Params {
    const float* w[24];  // [mod][wq,wk,wv,bq,bk,bv]
};

// ---------------------------------------------------------------- helpers
__device__ __forceinline__ uint32_t smem_to_u32(const void* p) {
    uint32_t a;
    asm("{ .reg .u64 t; cvta.to.shared.u64 t, %1; cvt.u32.u64 %0, t; }" : "=r"(a) : "l"(p));
    return a;
}
__device__ __forceinline__ uint32_t lds_u32(uint32_t a) {
    uint32_t v;
    asm volatile("ld.shared.b32 %0, [%1];" : "=r"(v) : "r"(a));
    return v;
}
__device__ __forceinline__ void mma16816(float* c, const uint32_t* a, uint32_t b0, uint32_t b1) {
    asm volatile("mma.sync.aligned.m16n8k16.row.col.f32.bf16.bf16.f32 "
        "{%0,%1,%2,%3}, {%4,%5,%6,%7}, {%8,%9}, {%0,%1,%2,%3};"
        : "+f"(c[0]), "+f"(c[1]), "+f"(c[2]), "+f"(c[3])
        : "r"(a[0]), "r"(a[1]), "r"(a[2]), "r"(a[3]), "r"(b0), "r"(b1));
}
__device__ __forceinline__ unsigned long long pack2(float x, float y) {
    unsigned long long r;
    asm("mov.b64 %0, {%1, %2};" : "=l"(r) : "f"(x), "f"(y));
    return r;
}
__device__ __forceinline__ void unpack2(unsigned long long v, float& x, float& y) {
    asm("mov.b64 {%0, %1}, %2;" : "=f"(x), "=f"(y) : "l"(v));
}
__device__ __forceinline__ void ffma2(unsigned long long& c, unsigned long long a, unsigned long long b) {
    asm("fma.rn.f32x2 %0, %1, %2, %0;" : "+l"(c) : "l"(a), "l"(b));
}

// ============================================================================
// prep_w: fp32 weights -> bf16 hi/lo
// ============================================================================
__global__ void prep_w(Params p) {
    const int seg = blockIdx.y;
    const int mod = seg / 3;
    const int Cin = (mod == 1) ? 1280 : 640;
    const size_t offs[12] = {0, 409600, 819200, 1228800, 2048000, 2867200,
                             3686400, 4096000, 4505600, 4915200, 5324800, 5734400};
    const float* __restrict__ w = p.w[mod * 6 + (seg % 3)];
    const size_t off = offs[seg];
    const size_t n = (size_t)640 * Cin;
    for (size_t i = (size_t)blockIdx.x * blockDim.x + threadIdx.x; i < n; i += (size_t)gridDim.x * blockDim.x) {
        float v = w[i];
        __nv_bfloat16 h = __float2bfloat16(v);
        g_w_hi[off + i] = h;
        g_w_lo[off + i] = __float2bfloat16(v - __bfloat162float(h));
    }
}

// ============================================================================
// prep_x: x[b][C=3200][L=100] fp32 -> XT[b][l][c] bf16 hi/lo
// ============================================================================
__global__ void prep_x(const float* __restrict__ x) {
    __shared__ float t[32][33];
    const int b = blockIdx.z, ct = blockIdx.x, lt = blockIdx.y;
    const int tx = threadIdx.x, ty = threadIdx.y;
    const float* xb = x + (size_t)b * 320000;
    const int l = lt * 32 + tx;
    #pragma unroll
    for (int j = 0; j < 4; j++) {
        int c = ct * 32 + ty + j * 8;
        t[ty + j * 8][tx] = (l < 100) ? xb[(size_t)c * 100 + l] : 0.0f;
    }
    __syncthreads();
    const int c_out = ct * 32 + tx;
    const size_t xtb = (size_t)b * 320000;
    #pragma unroll
    for (int j = 0; j < 4; j++) {
        int lo_ = lt * 32 + ty + j * 8;
        if (lo_ < 100) {
            float v = t[tx][ty + j * 8];
            __nv_bfloat16 h = __float2bfloat16(v);
            size_t o = xtb + (size_t)lo_ * 3200 + c_out;
            g_xt_hi[o] = h;
            g_xt_lo[o] = __float2bfloat16(v - __bfloat162float(h));
        }
    }
}

// ============================================================================
// qkv_mma: Y[128,104] tile via mma.sync bf16 3-term split.
// 8 warps x (16 rows x 13 n8-tiles). K-chunk 32, cp.async double buffer.
// smem row stride 80B ([row][k2] pairs, 16 data words + 4 pad) -> conflict-free
// fragment lds.
// ============================================================================
#define STAGE  37120u
#define OFF_AH 0u
#define OFF_AL 10240u
#define OFF_BH 20480u
#define OFF_BL 28800u

__global__ __launch_bounds__(256, 2) void qkv_mma(Params p) {
    extern __shared__ __align__(16) char smem_raw[];
    const uint32_t sb = smem_to_u32(smem_raw);

    const int tid = threadIdx.x;
    int bid = blockIdx.x;
    const int mtile = bid % 5; bid /= 5;
    const int proj  = bid % 3; bid /= 3;
    const int mod   = bid & 3;
    const int b     = bid >> 2;

    const int Cin = (mod == 1) ? 1280 : 640;
    const int nch = Cin >> 5;               // k-chunks of 32
    const int mbase = mtile * 128;

    const size_t offs[12] = {0, 409600, 819200, 1228800, 2048000, 2867200,
                             3686400, 4096000, 4505600, 4915200, 5324800, 5734400};
    const int c0m_tab[4] = {2560, 640, 1920, 0};
    const size_t woff = offs[mod * 3 + proj];
    const size_t xoff = (size_t)b * 320000 + c0m_tab[mod];
    const float* __restrict__ bias = p.w[mod * 6 + 3 + proj];
    float* __restrict__ O = g_scr + ((((size_t)b * 4 + mod) * 3 + proj) * 640 + mbase) * 100;

    const __nv_bfloat16* __restrict__ Wh = g_w_hi + woff;
    const __nv_bfloat16* __restrict__ Wl = g_w_lo + woff;
    const __nv_bfloat16* __restrict__ Xh = g_xt_hi + xoff;
    const __nv_bfloat16* __restrict__ Xl = g_xt_lo + xoff;

    // zero B pad rows 100..103 (both stages, hi+lo)
    for (int idx = tid; idx < 320; idx += 256) {
        int st = idx / 160, rest = idx % 160;
        int buf = rest / 80, r2 = rest % 80;
        uint32_t a = sb + (uint32_t)st * STAGE + (buf ? OFF_BL : OFF_BH)
                   + (uint32_t)(100 + r2 / 20) * 80 + (uint32_t)(r2 % 20) * 4;
        asm volatile("st.shared.b32 [%0], %1;" :: "r"(a), "r"(0) : "memory");
    }

    auto issue_chunk = [&](int st, int c) {
        const int k0 = c << 5;
        const uint32_t stg = sb + (uint32_t)st * STAGE;
        for (int idx = tid; idx < 1824; idx += 256) {
            const __nv_bfloat16* src;
            uint32_t dst;
            if (idx < 1024) {
                int buf = idx >> 9, r = (idx >> 2) & 127, seg = idx & 3;
                src = (buf ? Wl : Wh) + (size_t)(mbase + r) * Cin + k0 + seg * 8;
                dst = stg + (buf ? OFF_AL : OFF_AH) + (uint32_t)r * 80 + (uint32_t)seg * 16;
            } else {
                int j = idx - 1024;
                int n = j >> 3, rem = j & 7;
                int buf = rem >> 2, seg = rem & 3;
                src = (buf ? Xl : Xh) + (size_t)n * 3200 + k0 + seg * 8;
                dst = stg + (buf ? OFF_BL : OFF_BH) + (uint32_t)n * 80 + (uint32_t)seg * 16;
            }
            asm volatile("cp.async.cg.shared.global [%0], [%1], 16;" :: "r"(dst), "l"(src) : "memory");
        }
        asm volatile("cp.async.commit_group;" ::: "memory");
    };

    const int w = tid >> 5, lane = tid & 31;
    const int rloc = w * 16 + (lane >> 2);      // local row for c0/c1
    const int qd = lane & 3;
    const uint32_t nb = (uint32_t)(lane >> 2) * 80;

    float acc[13][4];
    #pragma unroll
    for (int t = 0; t < 13; t++)
        #pragma unroll
        for (int i = 0; i < 4; i++) acc[t][i] = 0.0f;

    issue_chunk(0, 0);

    for (int c = 0; c < nch; c++) {
        const int s = c & 1;
        if (c + 1 < nch) {
            issue_chunk(s ^ 1, c + 1);
            asm volatile("cp.async.wait_group 1;" ::: "memory");
        } else {
            asm volatile("cp.async.wait_group 0;" ::: "memory");
        }
        __syncthreads();

        const uint32_t stg = sb + (uint32_t)s * STAGE;
        const uint32_t aAh = stg + OFF_AH + (uint32_t)rloc * 80;
        const uint32_t aAl = stg + OFF_AL + (uint32_t)rloc * 80;
        const uint32_t aBh = stg + OFF_BH + nb;
        const uint32_t aBl = stg + OFF_BL + nb;

        #pragma unroll
        for (int s16 = 0; s16 < 2; s16++) {
            const uint32_t ko = (uint32_t)(8 * s16 + qd) * 4;
            uint32_t ah[4], al[4];
            ah[0] = lds_u32(aAh + ko);
            ah[1] = lds_u32(aAh + 640 + ko);        // +8 rows
            ah[2] = lds_u32(aAh + ko + 16);         // k2+4
            ah[3] = lds_u32(aAh + 640 + ko + 16);
            al[0] = lds_u32(aAl + ko);
            al[1] = lds_u32(aAl + 640 + ko);
            al[2] = lds_u32(aAl + ko + 16);
            al[3] = lds_u32(aAl + 640 + ko + 16);
            #pragma unroll
            for (int t = 0; t < 13; t++) {
                const uint32_t bo = (uint32_t)t * 640 + ko;
                uint32_t bh0 = lds_u32(aBh + bo);
                uint32_t bh1 = lds_u32(aBh + bo + 16);
                uint32_t bl0 = lds_u32(aBl + bo);
                uint32_t bl1 = lds_u32(aBl + bo + 16);
                mma16816(acc[t], ah, bh0, bh1);
                mma16816(acc[t], ah, bl0, bl1);
                mma16816(acc[t], al, bh0, bh1);
            }
        }
        __syncthreads();
    }

    // epilogue
    const float bv0 = bias[mbase + rloc];
    const float bv1 = bias[mbase + rloc + 8];
    float* o0 = O + (size_t)rloc * 100;
    float* o1 = o0 + 800;
    #pragma unroll
    for (int t = 0; t < 13; t++) {
        int col = t * 8 + qd * 2;
        if (col < 100) {
            float2 v0 = make_float2(acc[t][0] + bv0, acc[t][1] + bv0);
            float2 v1 = make_float2(acc[t][2] + bv1, acc[t][3] + bv1);
            *(float2*)(o0 + col) = v0;
            *(float2*)(o1 + col) = v1;
        }
    }
}

// ============================================================================
// Pass 2: attention (unchanged).
// ============================================================================
__global__ __launch_bounds__(256) void attn_kernel(float* __restrict__ out) {
    const int tid = threadIdx.x;
    int bid = blockIdx.x;
    const int half = bid & 1;
    const int bm   = bid >> 1;
    const int mod  = bm & 3;
    const int b    = bm >> 2;

    const float* __restrict__ Q = g_scr + (size_t)bm * 3 * 64000;
    const float* __restrict__ K = Q + 64000;
    const float* __restrict__ V = Q + 128000;
    float* __restrict__ O = out + ((size_t)mod * NB + b) * 64000;

    __shared__ __align__(16) float Ss[50][101];
    __shared__ __align__(16) float u[4864];

    const bool act = tid < 250;
    const int lg = tid % 25, mg = tid / 25;
    const int l0 = lg * 2, m0 = mg * 10;
    const int colQ = half * 50;

    unsigned long long sacc[10];
    #pragma unroll
    for (int j = 0; j < 10; j++) sacc[j] = 0ULL;

    for (int c0 = 0; c0 < 640; c0 += 32) {
        for (int idx = tid; idx < 800; idx += 256) {
            int row = idx / 25, c2 = (idx % 25) * 2;
            *(float2*)&u[row * 52 + c2] = *(const float2*)(Q + (size_t)(c0 + row) * 100 + colQ + c2);
        }
        for (int idx = tid; idx < 800; idx += 256) {
            int row = idx / 25, c4 = (idx % 25) * 4;
            *(float4*)&u[1664 + row * 100 + c4] = *(const float4*)(K + (size_t)(c0 + row) * 100 + c4);
        }
        __syncthreads();
        if (act) {
            #pragma unroll
            for (int kk = 0; kk < 32; kk++) {
                float2 q2 = *(const float2*)&u[kk * 52 + l0];
                unsigned long long qp = pack2(q2.x, q2.y);
                #pragma unroll
                for (int j = 0; j < 10; j++) {
                    float kv = u[1664 + kk * 100 + m0 + j];
                    ffma2(sacc[j], qp, pack2(kv, kv));
                }
            }
        }
        __syncthreads();
    }
    if (act) {
        #pragma unroll
        for (int j = 0; j < 10; j++) {
            float lo, hi;
            unpack2(sacc[j], lo, hi);
            Ss[l0][m0 + j]     = lo;
            Ss[l0 + 1][m0 + j] = hi;
        }
    }
    __syncthreads();

    {
        const int warp = tid >> 5, lane = tid & 31;
        for (int r = warp; r < 50; r += 8) {
            float v0 = Ss[r][lane];
            float v1 = Ss[r][lane + 32];
            float v2 = Ss[r][lane + 64];
            float v3 = (lane < 4) ? Ss[r][lane + 96] : -3.4e38f;
            float mx = fmaxf(fmaxf(v0, v1), fmaxf(v2, v3));
            #pragma unroll
            for (int o = 16; o; o >>= 1) mx = fmaxf(mx, __shfl_xor_sync(0xffffffffu, mx, o));
            v0 = __expf(v0 - mx);
            v1 = __expf(v1 - mx);
            v2 = __expf(v2 - mx);
            v3 = (lane < 4) ? __expf(v3 - mx) : 0.0f;
            float s = v0 + v1 + v2 + v3;
            #pragma unroll
            for (int o = 16; o; o >>= 1) s += __shfl_xor_sync(0xffffffffu, s, o);
            float inv = 1.0f / s;
            Ss[r][lane]      = v0 * inv;
            Ss[r][lane + 32] = v1 * inv;
            Ss[r][lane + 64] = v2 * inv;
            if (lane < 4) Ss[r][lane + 96] = v3 * inv;
        }
    }

    const int cg = tid % 10, ig = tid / 10;
    const bool actC = tid < 250;
    const int cl0 = cg * 4, i0 = ig * 2;

    for (int chunk = 0; chunk < 16; chunk++) {
        __syncthreads();
        for (int idx = tid; idx < 1000; idx += 256) {
            int row = idx / 25, c4 = (idx % 25) * 4;
            float4 v = *(const float4*)(V + (size_t)(chunk * 40 + row) * 100 + c4);
            u[row * 101 + c4 + 0] = v.x;
            u[row * 101 + c4 + 1] = v.y;
            u[row * 101 + c4 + 2] = v.z;
            u[row * 101 + c4 + 3] = v.w;
        }
        __syncthreads();
        if (actC) {
            float acc[4][2] = {};
            #pragma unroll 4
            for (int j = 0; j < 100; j++) {
                float p0 = Ss[i0][j], p1 = Ss[i0 + 1][j];
                #pragma unroll
                for (int uu = 0; uu < 4; uu++) {
                    float vv = u[(cl0 + uu) * 101 + j];
                    acc[uu][0] += vv * p0;
                    acc[uu][1] += vv * p1;
                }
            }
            #pragma unroll
            for (int uu = 0; uu < 4; uu++) {
                int c = chunk * 40 + cl0 + uu;
                O[(size_t)c * 100 + half * 50 + i0]     = acc[uu][0];
                O[(size_t)c * 100 + half * 50 + i0 + 1] = acc[uu][1];
            }
        }
    }
}

extern "C" void kernel_launch(void* const* d_in, const int* in_sizes, int n_in,
                              void* d_out, int out_size) {
    const float* x = (const float*)d_in[0];
    Params p;
    for (int i = 0; i < 24; i++) p.w[i] = (const float*)d_in[1 + i];

    prep_w<<<dim3(800, 12), 256>>>(p);
    prep_x<<<dim3(100, 4, 256), dim3(32, 8)>>>(x);

    cudaFuncSetAttribute(qkv_mma, cudaFuncAttributeMaxDynamicSharedMemorySize, 74240);
    qkv_mma<<<15360, 256, 74240>>>(p);

    attn_kernel<<<2048, 256>>>((float*)d_out);
}

// round 6
// speedup vs baseline: 2.2668x; 1.0652x over previous
#include <cuda_runtime.h>
#include <cuda_bf16.h>
#include <cstdint>

#define NB 256

// Scratch: [b][mod][proj(Q,K,V)][640][100] fp32
__device__ float g_scr[196608000UL];
__device__ __nv_bfloat16 g_w_hi[6144000];
__device__ __nv_bfloat16 g_w_lo[6144000];
__device__ __nv_bfloat16 g_xt_hi[81920000UL];   // [b][l=100][c=3200]
__device__ __nv_bfloat16 g_xt_lo[81920000UL];

struct Params {
    const float* w[24];  // [mod][wq,wk,wv,bq,bk,bv]
};

// ---------------------------------------------------------------- helpers
__device__ __forceinline__ uint32_t smem_to_u32(const void* p) {
    uint32_t a;
    asm("{ .reg .u64 t; cvta.to.shared.u64 t, %1; cvt.u32.u64 %0, t; }" : "=r"(a) : "l"(p));
    return a;
}
__device__ __forceinline__ void ldsm4(uint32_t* r, uint32_t addr) {
    asm volatile("ldmatrix.sync.aligned.m8n8.x4.shared.b16 {%0,%1,%2,%3}, [%4];"
        : "=r"(r[0]), "=r"(r[1]), "=r"(r[2]), "=r"(r[3]) : "r"(addr));
}
__device__ __forceinline__ void ldsm2(uint32_t* r, uint32_t addr) {
    asm volatile("ldmatrix.sync.aligned.m8n8.x2.shared.b16 {%0,%1}, [%2];"
        : "=r"(r[0]), "=r"(r[1]) : "r"(addr));
}
__device__ __forceinline__ void mma16816(float* c, const uint32_t* a, uint32_t b0, uint32_t b1) {
    asm volatile("mma.sync.aligned.m16n8k16.row.col.f32.bf16.bf16.f32 "
        "{%0,%1,%2,%3}, {%4,%5,%6,%7}, {%8,%9}, {%0,%1,%2,%3};"
        : "+f"(c[0]), "+f"(c[1]), "+f"(c[2]), "+f"(c[3])
        : "r"(a[0]), "r"(a[1]), "r"(a[2]), "r"(a[3]), "r"(b0), "r"(b1));
}
__device__ __forceinline__ unsigned long long pack2(float x, float y) {
    unsigned long long r;
    asm("mov.b64 %0, {%1, %2};" : "=l"(r) : "f"(x), "f"(y));
    return r;
}
__device__ __forceinline__ void unpack2(unsigned long long v, float& x, float& y) {
    asm("mov.b64 {%0, %1}, %2;" : "=f"(x), "=f"(y) : "l"(v));
}
__device__ __forceinline__ void ffma2(unsigned long long& c, unsigned long long a, unsigned long long b) {
    asm("fma.rn.f32x2 %0, %1, %2, %0;" : "+l"(c) : "l"(a), "l"(b));
}

// ============================================================================
// prep_w: fp32 weights -> bf16 hi/lo
// ============================================================================
__global__ void prep_w(Params p) {
    const int seg = blockIdx.y;
    const int mod = seg / 3;
    const int Cin = (mod == 1) ? 1280 : 640;
    const size_t offs[12] = {0, 409600, 819200, 1228800, 2048000, 2867200,
                             3686400, 4096000, 4505600, 4915200, 5324800, 5734400};
    const float* __restrict__ w = p.w[mod * 6 + (seg % 3)];
    const size_t off = offs[seg];
    const size_t n = (size_t)640 * Cin;
    for (size_t i = (size_t)blockIdx.x * blockDim.x + threadIdx.x; i < n; i += (size_t)gridDim.x * blockDim.x) {
        float v = w[i];
        __nv_bfloat16 h = __float2bfloat16(v);
        g_w_hi[off + i] = h;
        g_w_lo[off + i] = __float2bfloat16(v - __bfloat162float(h));
    }
}

// ============================================================================
// prep_x: x[b][C=3200][L=100] fp32 -> XT[b][l][c] bf16 hi/lo
// ============================================================================
__global__ void prep_x(const float* __restrict__ x) {
    __shared__ float t[32][33];
    const int b = blockIdx.z, ct = blockIdx.x, lt = blockIdx.y;
    const int tx = threadIdx.x, ty = threadIdx.y;
    const float* xb = x + (size_t)b * 320000;
    const int l = lt * 32 + tx;
    #pragma unroll
    for (int j = 0; j < 4; j++) {
        int c = ct * 32 + ty + j * 8;
        t[ty + j * 8][tx] = (l < 100) ? xb[(size_t)c * 100 + l] : 0.0f;
    }
    __syncthreads();
    const int c_out = ct * 32 + tx;
    const size_t xtb = (size_t)b * 320000;
    #pragma unroll
    for (int j = 0; j < 4; j++) {
        int lo_ = lt * 32 + ty + j * 8;
        if (lo_ < 100) {
            float v = t[tx][ty + j * 8];
            __nv_bfloat16 h = __float2bfloat16(v);
            size_t o = xtb + (size_t)lo_ * 3200 + c_out;
            g_xt_hi[o] = h;
            g_xt_lo[o] = __float2bfloat16(v - __bfloat162float(h));
        }
    }
}

// ============================================================================
// qkv_mma: Y[128,104] tile via mma.sync bf16 3-term split (ldmatrix loads).
// 8 warps x (16 rows x 13 n8-tiles). K-chunk 32, cp.async double buffer.
// ============================================================================
#define STAGE  37120u
#define OFF_AH 0u
#define OFF_AL 10240u
#define OFF_BH 20480u
#define OFF_BL 28800u

__global__ __launch_bounds__(256, 2) void qkv_mma(Params p) {
    extern __shared__ __align__(16) char smem_raw[];
    const uint32_t sb = smem_to_u32(smem_raw);

    const int tid = threadIdx.x;
    int bid = blockIdx.x;
    const int mtile = bid % 5; bid /= 5;
    const int proj  = bid % 3; bid /= 3;
    const int mod   = bid & 3;
    const int b     = bid >> 2;

    const int Cin = (mod == 1) ? 1280 : 640;
    const int nch = Cin >> 5;               // k-chunks of 32
    const int mbase = mtile * 128;

    const size_t offs[12] = {0, 409600, 819200, 1228800, 2048000, 2867200,
                             3686400, 4096000, 4505600, 4915200, 5324800, 5734400};
    const int c0m_tab[4] = {2560, 640, 1920, 0};
    const size_t woff = offs[mod * 3 + proj];
    const size_t xoff = (size_t)b * 320000 + c0m_tab[mod];
    const float* __restrict__ bias = p.w[mod * 6 + 3 + proj];
    float* __restrict__ O = g_scr + ((((size_t)b * 4 + mod) * 3 + proj) * 640 + mbase) * 100;

    const __nv_bfloat16* __restrict__ Wh = g_w_hi + woff;
    const __nv_bfloat16* __restrict__ Wl = g_w_lo + woff;
    const __nv_bfloat16* __restrict__ Xh = g_xt_hi + xoff;
    const __nv_bfloat16* __restrict__ Xl = g_xt_lo + xoff;

    // zero B pad rows 100..103 (both stages, hi+lo)
    for (int idx = tid; idx < 320; idx += 256) {
        int st = idx / 160, rest = idx % 160;
        int buf = rest / 80, r2 = rest % 80;
        uint32_t a = sb + (uint32_t)st * STAGE + (buf ? OFF_BL : OFF_BH)
                   + (uint32_t)(100 + r2 / 20) * 80 + (uint32_t)(r2 % 20) * 4;
        asm volatile("st.shared.b32 [%0], %1;" :: "r"(a), "r"(0) : "memory");
    }

    auto issue_chunk = [&](int st, int c) {
        const int k0 = c << 5;
        const uint32_t stg = sb + (uint32_t)st * STAGE;
        for (int idx = tid; idx < 1824; idx += 256) {
            const __nv_bfloat16* src;
            uint32_t dst;
            if (idx < 1024) {
                int buf = idx >> 9, r = (idx >> 2) & 127, seg = idx & 3;
                src = (buf ? Wl : Wh) + (size_t)(mbase + r) * Cin + k0 + seg * 8;
                dst = stg + (buf ? OFF_AL : OFF_AH) + (uint32_t)r * 80 + (uint32_t)seg * 16;
            } else {
                int j = idx - 1024;
                int n = j >> 3, rem = j & 7;
                int buf = rem >> 2, seg = rem & 3;
                src = (buf ? Xl : Xh) + (size_t)n * 3200 + k0 + seg * 8;
                dst = stg + (buf ? OFF_BL : OFF_BH) + (uint32_t)n * 80 + (uint32_t)seg * 16;
            }
            asm volatile("cp.async.cg.shared.global [%0], [%1], 16;" :: "r"(dst), "l"(src) : "memory");
        }
        asm volatile("cp.async.commit_group;" ::: "memory");
    };

    const int w = tid >> 5, lane = tid & 31;
    const int rloc = w * 16 + (lane >> 2);
    const int qd = lane & 3;

    // ldmatrix lane-address offsets
    // A x4: matrices {m0-7/k0-7, m8-15/k0-7, m0-7/k8-15, m8-15/k8-15}
    const uint32_t aoff = (uint32_t)(w * 16 + (lane & 15)) * 80 + (uint32_t)(lane >> 4) * 16;
    // B x4 (pair of n8 tiles): {t0/k0-7, t0/k8-15, t1/k0-7, t1/k8-15}
    const uint32_t b4off = (uint32_t)(((lane >> 4) * 8) + (lane & 7)) * 80 + (uint32_t)((lane >> 3) & 1) * 16;
    // B x2 (last tile, lanes 0-15 meaningful)
    const uint32_t b2off = (uint32_t)(lane & 7) * 80 + (uint32_t)((lane >> 3) & 1) * 16;

    float acc[13][4];
    #pragma unroll
    for (int t = 0; t < 13; t++)
        #pragma unroll
        for (int i = 0; i < 4; i++) acc[t][i] = 0.0f;

    issue_chunk(0, 0);

    for (int c = 0; c < nch; c++) {
        const int s = c & 1;
        if (c + 1 < nch) {
            issue_chunk(s ^ 1, c + 1);
            asm volatile("cp.async.wait_group 1;" ::: "memory");
        } else {
            asm volatile("cp.async.wait_group 0;" ::: "memory");
        }
        __syncthreads();

        const uint32_t stg = sb + (uint32_t)s * STAGE;
        const uint32_t aAh = stg + OFF_AH + aoff;
        const uint32_t aAl = stg + OFF_AL + aoff;
        const uint32_t aBh4 = stg + OFF_BH + b4off;
        const uint32_t aBl4 = stg + OFF_BL + b4off;
        const uint32_t aBh2 = stg + OFF_BH + 7680u + b2off;   // tile 12: rows 96..103
        const uint32_t aBl2 = stg + OFF_BL + 7680u + b2off;

        #pragma unroll
        for (int s16 = 0; s16 < 2; s16++) {
            const uint32_t ko = (uint32_t)s16 * 32;
            uint32_t ah[4], al[4];
            ldsm4(ah, aAh + ko);
            ldsm4(al, aAl + ko);
            #pragma unroll
            for (int pr = 0; pr < 6; pr++) {
                uint32_t bh[4], bl[4];
                ldsm4(bh, aBh4 + (uint32_t)pr * 1280 + ko);
                ldsm4(bl, aBl4 + (uint32_t)pr * 1280 + ko);
                mma16816(acc[2 * pr], ah, bh[0], bh[1]);
                mma16816(acc[2 * pr], ah, bl[0], bl[1]);
                mma16816(acc[2 * pr], al, bh[0], bh[1]);
                mma16816(acc[2 * pr + 1], ah, bh[2], bh[3]);
                mma16816(acc[2 * pr + 1], ah, bl[2], bl[3]);
                mma16816(acc[2 * pr + 1], al, bh[2], bh[3]);
            }
            {
                uint32_t bh[2], bl[2];
                ldsm2(bh, aBh2 + ko);
                ldsm2(bl, aBl2 + ko);
                mma16816(acc[12], ah, bh[0], bh[1]);
                mma16816(acc[12], ah, bl[0], bl[1]);
                mma16816(acc[12], al, bh[0], bh[1]);
            }
        }
        __syncthreads();
    }

    // epilogue
    const float bv0 = bias[mbase + rloc];
    const float bv1 = bias[mbase + rloc + 8];
    float* o0 = O + (size_t)rloc * 100;
    float* o1 = o0 + 800;
    #pragma unroll
    for (int t = 0; t < 13; t++) {
        int col = t * 8 + qd * 2;
        if (col < 100) {
            float2 v0 = make_float2(acc[t][0] + bv0, acc[t][1] + bv0);
            float2 v1 = make_float2(acc[t][2] + bv1, acc[t][3] + bv1);
            *(float2*)(o0 + col) = v0;
            *(float2*)(o1 + col) = v1;
        }
    }
}

// ============================================================================
// Pass 2: attention (unchanged).
// ============================================================================
__global__ __launch_bounds__(256) void attn_kernel(float* __restrict__ out) {
    const int tid = threadIdx.x;
    int bid = blockIdx.x;
    const int half = bid & 1;
    const int bm   = bid >> 1;
    const int mod  = bm & 3;
    const int b    = bm >> 2;

    const float* __restrict__ Q = g_scr + (size_t)bm * 3 * 64000;
    const float* __restrict__ K = Q + 64000;
    const float* __restrict__ V = Q + 128000;
    float* __restrict__ O = out + ((size_t)mod * NB + b) * 64000;

    __shared__ __align__(16) float Ss[50][101];
    __shared__ __align__(16) float u[4864];

    const bool act = tid < 250;
    const int lg = tid % 25, mg = tid / 25;
    const int l0 = lg * 2, m0 = mg * 10;
    const int colQ = half * 50;

    unsigned long long sacc[10];
    #pragma unroll
    for (int j = 0; j < 10; j++) sacc[j] = 0ULL;

    for (int c0 = 0; c0 < 640; c0 += 32) {
        for (int idx = tid; idx < 800; idx += 256) {
            int row = idx / 25, c2 = (idx % 25) * 2;
            *(float2*)&u[row * 52 + c2] = *(const float2*)(Q + (size_t)(c0 + row) * 100 + colQ + c2);
        }
        for (int idx = tid; idx < 800; idx += 256) {
            int row = idx / 25, c4 = (idx % 25) * 4;
            *(float4*)&u[1664 + row * 100 + c4] = *(const float4*)(K + (size_t)(c0 + row) * 100 + c4);
        }
        __syncthreads();
        if (act) {
            #pragma unroll
            for (int kk = 0; kk < 32; kk++) {
                float2 q2 = *(const float2*)&u[kk * 52 + l0];
                unsigned long long qp = pack2(q2.x, q2.y);
                #pragma unroll
                for (int j = 0; j < 10; j++) {
                    float kv = u[1664 + kk * 100 + m0 + j];
                    ffma2(sacc[j], qp, pack2(kv, kv));
                }
            }
        }
        __syncthreads();
    }
    if (act) {
        #pragma unroll
        for (int j = 0; j < 10; j++) {
            float lo, hi;
            unpack2(sacc[j], lo, hi);
            Ss[l0][m0 + j]     = lo;
            Ss[l0 + 1][m0 + j] = hi;
        }
    }
    __syncthreads();

    {
        const int warp = tid >> 5, lane = tid & 31;
        for (int r = warp; r < 50; r += 8) {
            float v0 = Ss[r][lane];
            float v1 = Ss[r][lane + 32];
            float v2 = Ss[r][lane + 64];
            float v3 = (lane < 4) ? Ss[r][lane + 96] : -3.4e38f;
            float mx = fmaxf(fmaxf(v0, v1), fmaxf(v2, v3));
            #pragma unroll
            for (int o = 16; o; o >>= 1) mx = fmaxf(mx, __shfl_xor_sync(0xffffffffu, mx, o));
            v0 = __expf(v0 - mx);
            v1 = __expf(v1 - mx);
            v2 = __expf(v2 - mx);
            v3 = (lane < 4) ? __expf(v3 - mx) : 0.0f;
            float s = v0 + v1 + v2 + v3;
            #pragma unroll
            for (int o = 16; o; o >>= 1) s += __shfl_xor_sync(0xffffffffu, s, o);
            float inv = 1.0f / s;
            Ss[r][lane]      = v0 * inv;
            Ss[r][lane + 32] = v1 * inv;
            Ss[r][lane + 64] = v2 * inv;
            if (lane < 4) Ss[r][lane + 96] = v3 * inv;
        }
    }

    const int cg = tid % 10, ig = tid / 10;
    const bool actC = tid < 250;
    const int cl0 = cg * 4, i0 = ig * 2;

    for (int chunk = 0; chunk < 16; chunk++) {
        __syncthreads();
        for (int idx = tid; idx < 1000; idx += 256) {
            int row = idx / 25, c4 = (idx % 25) * 4;
            float4 v = *(const float4*)(V + (size_t)(chunk * 40 + row) * 100 + c4);
            u[row * 101 + c4 + 0] = v.x;
            u[row * 101 + c4 + 1] = v.y;
            u[row * 101 + c4 + 2] = v.z;
            u[row * 101 + c4 + 3] = v.w;
        }
        __syncthreads();
        if (actC) {
            float acc[4][2] = {};
            #pragma unroll 4
            for (int j = 0; j < 100; j++) {
                float p0 = Ss[i0][j], p1 = Ss[i0 + 1][j];
                #pragma unroll
                for (int uu = 0; uu < 4; uu++) {
                    float vv = u[(cl0 + uu) * 101 + j];
                    acc[uu][0] += vv * p0;
                    acc[uu][1] += vv * p1;
                }
            }
            #pragma unroll
            for (int uu = 0; uu < 4; uu++) {
                int c = chunk * 40 + cl0 + uu;
                O[(size_t)c * 100 + half * 50 + i0]     = acc[uu][0];
                O[(size_t)c * 100 + half * 50 + i0 + 1] = acc[uu][1];
            }
        }
    }
}

extern "C" void kernel_launch(void* const* d_in, const int* in_sizes, int n_in,
                              void* d_out, int out_size) {
    const float* x = (const float*)d_in[0];
    Params p;
    for (int i = 0; i < 24; i++) p.w[i] = (const float*)d_in[1 + i];

    prep_w<<<dim3(800, 12), 256>>>(p);
    prep_x<<<dim3(100, 4, 256), dim3(32, 8)>>>(x);

    cudaFuncSetAttribute(qkv_mma, cudaFuncAttributeMaxDynamicSharedMemorySize, 74240);
    qkv_mma<<<15360, 256, 74240>>>(p);

    attn_kernel<<<2048, 256>>>((float*)d_out);
}